// round 1
// baseline (speedup 1.0000x reference)
#include <cuda_runtime.h>
#include <math.h>

// Problem constants
#define BATCH 8
#define SEQ   2048
#define FDIM  512
#define DDIM  512
#define MTOT  (BATCH * SEQ)   // 16384

// Scratch (allocation-free rule -> __device__ globals)
__device__ float g_xpe[(size_t)MTOT * FDIM];          // 33.5 MB
__device__ float g_Q[(size_t)MTOT * DDIM];            // 33.5 MB
__device__ float g_K[(size_t)MTOT * DDIM];            // 33.5 MB
__device__ float g_V[(size_t)MTOT * DDIM];            // 33.5 MB
__device__ float g_scores[(size_t)BATCH * SEQ * SEQ]; // 134 MB

// ---------------------------------------------------------------------------
// 128x128x8 fp32 tiled GEMM body, 256 threads, 8x8 per-thread microtile.
// BT=false: C[MxN] = A[MxK] * B[KxN]   (both row-major)
// BT=true : C[MxN] = A[MxK] * B[NxK]^T (B row-major [N,K], dot of rows)
// All dims assumed multiples of tile sizes (true for this problem).
// ---------------------------------------------------------------------------
template <bool BT>
__device__ __forceinline__ void gemm_body(const float* __restrict__ A,
                                          const float* __restrict__ Bm,
                                          float* __restrict__ C,
                                          int N, int K, float alpha)
{
    __shared__ float As[8][128];
    __shared__ float Bs[8][128];

    const int tid  = threadIdx.x;
    const int tx   = tid & 15;   // 0..15 (N dir)
    const int ty   = tid >> 4;   // 0..15 (M dir)
    const int row0 = blockIdx.y * 128;
    const int col0 = blockIdx.x * 128;

    // A tile loader: each thread loads one float4 along K
    const int ar = tid >> 1;          // 0..127
    const int ac = (tid & 1) << 2;    // 0 or 4
    const float* Ap = A + (size_t)(row0 + ar) * K + ac;

    // B tile loader
    const float* Bp;
    int br, bc;
    if (BT) {
        br = tid >> 1;               // 0..127 (N index)
        bc = (tid & 1) << 2;         // K offset
        Bp = Bm + (size_t)(col0 + br) * K + bc;
    } else {
        br = tid >> 5;               // 0..7 (K index)
        bc = (tid & 31) << 2;        // 0..124 (N offset)
        Bp = Bm + (size_t)br * N + col0 + bc;
    }

    float acc[8][8];
#pragma unroll
    for (int i = 0; i < 8; i++)
#pragma unroll
        for (int j = 0; j < 8; j++) acc[i][j] = 0.0f;

    for (int k0 = 0; k0 < K; k0 += 8) {
        float4 a4 = *(const float4*)(Ap + k0);
        As[ac + 0][ar] = a4.x;
        As[ac + 1][ar] = a4.y;
        As[ac + 2][ar] = a4.z;
        As[ac + 3][ar] = a4.w;
        if (BT) {
            float4 b4 = *(const float4*)(Bp + k0);
            Bs[bc + 0][br] = b4.x;
            Bs[bc + 1][br] = b4.y;
            Bs[bc + 2][br] = b4.z;
            Bs[bc + 3][br] = b4.w;
        } else {
            float4 b4 = *(const float4*)(Bp + (size_t)k0 * N);
            *(float4*)&Bs[br][bc] = b4;
        }
        __syncthreads();

#pragma unroll
        for (int kk = 0; kk < 8; kk++) {
            float af[8], bf[8];
            *(float4*)(af)     = *(const float4*)(&As[kk][ty * 8]);
            *(float4*)(af + 4) = *(const float4*)(&As[kk][ty * 8 + 4]);
            *(float4*)(bf)     = *(const float4*)(&Bs[kk][tx * 8]);
            *(float4*)(bf + 4) = *(const float4*)(&Bs[kk][tx * 8 + 4]);
#pragma unroll
            for (int i = 0; i < 8; i++)
#pragma unroll
                for (int j = 0; j < 8; j++)
                    acc[i][j] += af[i] * bf[j];
        }
        __syncthreads();
    }

#pragma unroll
    for (int i = 0; i < 8; i++) {
        float* Cp = C + (size_t)(row0 + ty * 8 + i) * N + col0 + tx * 8;
        float4 v0 = make_float4(alpha * acc[i][0], alpha * acc[i][1],
                                alpha * acc[i][2], alpha * acc[i][3]);
        float4 v1 = make_float4(alpha * acc[i][4], alpha * acc[i][5],
                                alpha * acc[i][6], alpha * acc[i][7]);
        *(float4*)Cp       = v0;
        *(float4*)(Cp + 4) = v1;
    }
}

// ---------------------------------------------------------------------------
// Kernel 1: xpe = x + sinusoidal PE.
// Reference: angle = pos / 10000^{(2*(f//2))/F} (fp32), sin on even f, cos odd.
// Range-reduce the fp32 angle in double so accuracy is immune to fast-math
// __sinf degradation at |angle| up to 2047.
// ---------------------------------------------------------------------------
__global__ void __launch_bounds__(256) k_addpe(const float* __restrict__ x)
{
    size_t idx = (size_t)blockIdx.x * 256 + threadIdx.x;
    int f = (int)(idx & (FDIM - 1));
    int s = (int)((idx >> 9) & (SEQ - 1));
    float e     = (float)(f & ~1) * (1.0f / (float)FDIM);
    float denom = powf(10000.0f, e);
    float angle = (float)s / denom;          // matches reference fp32 rounding
    double r = fmod((double)angle, 6.283185307179586476925286766559);
    float a = (float)r;
    float pe = (f & 1) ? cosf(a) : sinf(a);
    g_xpe[idx] = x[idx] + pe;
}

// Kernel 2: QKV projections. z selects {Wq->Q, Wk->K, Wv->V}.
__global__ void __launch_bounds__(256) k_proj(const float* __restrict__ Wq,
                                              const float* __restrict__ Wk,
                                              const float* __restrict__ Wv)
{
    const float* W = (blockIdx.z == 0) ? Wq : (blockIdx.z == 1) ? Wk : Wv;
    float* Cout    = (blockIdx.z == 0) ? g_Q : (blockIdx.z == 1) ? g_K : g_V;
    gemm_body<false>(g_xpe, W, Cout, DDIM, FDIM, 1.0f);
}

// Kernel 3: scores[b,i,j] = (1/sqrt(D)) * Q[b,i,:] . K[b,j,:]   (NT)
__global__ void __launch_bounds__(256) k_scores()
{
    size_t b = blockIdx.z;
    gemm_body<true>(g_Q + b * (size_t)SEQ * DDIM,
                    g_K + b * (size_t)SEQ * DDIM,
                    g_scores + b * (size_t)SEQ * SEQ,
                    SEQ, DDIM, 0.04419417382415922f /* 1/sqrt(512) */);
}

// Kernel 4: row softmax over 2048 columns, one block per row.
__global__ void __launch_bounds__(256) k_softmax()
{
    float* p = g_scores + (size_t)blockIdx.x * SEQ;
    const int tid = threadIdx.x;
    float v[8];
    float m = -1e30f;
#pragma unroll
    for (int i = 0; i < 8; i++) {
        v[i] = p[tid + i * 256];
        m = fmaxf(m, v[i]);
    }
    __shared__ float sh[8];
#pragma unroll
    for (int o = 16; o > 0; o >>= 1)
        m = fmaxf(m, __shfl_xor_sync(0xffffffffu, m, o));
    if ((tid & 31) == 0) sh[tid >> 5] = m;
    __syncthreads();
    m = sh[0];
#pragma unroll
    for (int w = 1; w < 8; w++) m = fmaxf(m, sh[w]);

    float s = 0.0f;
#pragma unroll
    for (int i = 0; i < 8; i++) {
        v[i] = expf(v[i] - m);
        s += v[i];
    }
#pragma unroll
    for (int o = 16; o > 0; o >>= 1)
        s += __shfl_xor_sync(0xffffffffu, s, o);
    __syncthreads();                 // protect sh reuse
    if ((tid & 31) == 0) sh[tid >> 5] = s;
    __syncthreads();
    s = 0.0f;
#pragma unroll
    for (int w = 0; w < 8; w++) s += sh[w];
    float inv = 1.0f / s;
#pragma unroll
    for (int i = 0; i < 8; i++) p[tid + i * 256] = v[i] * inv;
}

// Kernel 5: out[b,i,d] = attn[b,i,:] . V[b,:,d]   (NN)
__global__ void __launch_bounds__(256) k_out(float* __restrict__ out)
{
    size_t b = blockIdx.z;
    gemm_body<false>(g_scores + b * (size_t)SEQ * SEQ,
                     g_V + b * (size_t)SEQ * DDIM,
                     out + b * (size_t)SEQ * DDIM,
                     DDIM, SEQ, 1.0f);
}

extern "C" void kernel_launch(void* const* d_in, const int* in_sizes, int n_in,
                              void* d_out, int out_size)
{
    const float* x  = (const float*)d_in[0];
    const float* Wq = (const float*)d_in[1];
    const float* Wk = (const float*)d_in[2];
    const float* Wv = (const float*)d_in[3];
    float* out = (float*)d_out;

    k_addpe<<<((size_t)MTOT * FDIM) / 256, 256>>>(x);
    k_proj<<<dim3(DDIM / 128, MTOT / 128, 3), 256>>>(Wq, Wk, Wv);
    k_scores<<<dim3(SEQ / 128, SEQ / 128, BATCH), 256>>>();
    k_softmax<<<BATCH * SEQ, 256>>>();
    k_out<<<dim3(DDIM / 128, SEQ / 128, BATCH), 256>>>(out);
}

// round 4
// speedup vs baseline: 2.5347x; 2.5347x over previous
#include <cuda_runtime.h>
#include <cuda_bf16.h>
#include <math.h>
#include <stdint.h>

#define BATCH 8
#define SEQ   2048
#define FDIM  512
#define DDIM  512
#define MTOT  (BATCH * SEQ)   // 16384

// ---------------- scratch (__device__ globals; no allocs allowed) ----------
__device__ __nv_bfloat16 g_xpe_h[(size_t)MTOT * FDIM];
__device__ __nv_bfloat16 g_xpe_l[(size_t)MTOT * FDIM];
__device__ __nv_bfloat16 g_Wt_h[3 * FDIM * DDIM];      // [z][n][k] (W transposed)
__device__ __nv_bfloat16 g_Wt_l[3 * FDIM * DDIM];
__device__ __nv_bfloat16 g_Q_h[(size_t)MTOT * DDIM];
__device__ __nv_bfloat16 g_Q_l[(size_t)MTOT * DDIM];
__device__ __nv_bfloat16 g_K_h[(size_t)MTOT * DDIM];
__device__ __nv_bfloat16 g_K_l[(size_t)MTOT * DDIM];
__device__ __nv_bfloat16 g_V_h[(size_t)MTOT * DDIM];
__device__ __nv_bfloat16 g_V_l[(size_t)MTOT * DDIM];
__device__ __nv_bfloat16 g_Vt_h[(size_t)MTOT * DDIM];  // [b][d][j]
__device__ __nv_bfloat16 g_Vt_l[(size_t)MTOT * DDIM];
__device__ float         g_scores[(size_t)BATCH * SEQ * SEQ];     // 134MB
__device__ __nv_bfloat16 g_attn_h[(size_t)BATCH * SEQ * SEQ];
__device__ __nv_bfloat16 g_attn_l[(size_t)BATCH * SEQ * SEQ];

// ---------------- PTX helpers ----------------------------------------------
__device__ __forceinline__ uint32_t s2u(const void* p) {
    return (uint32_t)__cvta_generic_to_shared(p);
}
__device__ __forceinline__ void cpa16(uint32_t dst, const void* src) {
    asm volatile("cp.async.cg.shared.global [%0], [%1], 16;\n" :: "r"(dst), "l"(src));
}
#define CP_COMMIT()  asm volatile("cp.async.commit_group;\n" ::: "memory")
#define CP_WAIT2()   asm volatile("cp.async.wait_group 2;\n" ::: "memory")

#define LDM4(r, addr) \
    asm volatile("ldmatrix.sync.aligned.m8n8.x4.shared.b16 {%0,%1,%2,%3}, [%4];" \
                 : "=r"((r)[0]), "=r"((r)[1]), "=r"((r)[2]), "=r"((r)[3]) : "r"(addr))

#define MMA16816(d, a, b0, b1) \
    asm volatile("mma.sync.aligned.m16n8k16.row.col.f32.bf16.bf16.f32 " \
                 "{%0,%1,%2,%3}, {%4,%5,%6,%7}, {%8,%9}, {%0,%1,%2,%3};" \
                 : "+f"((d)[0]), "+f"((d)[1]), "+f"((d)[2]), "+f"((d)[3]) \
                 : "r"((a)[0]), "r"((a)[1]), "r"((a)[2]), "r"((a)[3]), \
                   "r"(b0), "r"(b1))

// ---------------- GEMM: CTA 128x128, K-chunk 32, bf16x3, HMMA --------------
// smem per stage: 4 planes (Ah, Al, Bh, Bl), each 128 rows x 80B (32 bf16 + pad)
#define PLANE_B    10240
#define STAGE_B    40960
#define SMEM_TOTAL (4 * STAGE_B)   // 163840

__device__ __forceinline__ void ld_stage(uint32_t sb,
    const __nv_bfloat16* Ah, const __nv_bfloat16* Al,
    const __nv_bfloat16* Bh, const __nv_bfloat16* Bl,
    int K, int k0, int tid)
{
#pragma unroll
    for (int i = 0; i < 2; i++) {
        int ci = tid + i * 256;
        int r = ci >> 2, c = ci & 3;
        size_t ge = (size_t)r * K + k0 + c * 8;   // bf16 element offset
        uint32_t so = r * 80 + c * 16;
        cpa16(sb + so,               Ah + ge);
        cpa16(sb + PLANE_B + so,     Al + ge);
        cpa16(sb + 2 * PLANE_B + so, Bh + ge);
        cpa16(sb + 3 * PLANE_B + so, Bl + ge);
    }
}

// EPI 0: fp32 C with alpha.  EPI 1: bf16 hi/lo split planes.
template <int EPI>
__device__ __forceinline__ void gemm_core(
    const __nv_bfloat16* __restrict__ Ah, const __nv_bfloat16* __restrict__ Al,
    const __nv_bfloat16* __restrict__ Bh, const __nv_bfloat16* __restrict__ Bl,
    int K, float alpha,
    float* __restrict__ C, int ldC,
    __nv_bfloat16* __restrict__ Ch, __nv_bfloat16* __restrict__ Cl)
{
    extern __shared__ __align__(128) char sm[];
    const uint32_t smb = s2u(sm);
    const int tid = threadIdx.x;
    const int w = tid >> 5, lane = tid & 31;
    const int wr = w & 1, wc = w >> 1;         // warp grid 2 (M) x 4 (N)
    const int q = lane & 7, sel = lane >> 3;   // ldmatrix addressing
    const int g = lane >> 2, t = lane & 3;     // fragment addressing

    // per-thread ldmatrix smem byte offsets (within plane); ks adds ks*32
    uint32_t aoff[4], boff[2];
#pragma unroll
    for (int mt = 0; mt < 4; mt++)
        aoff[mt] = (uint32_t)(wr * 64 + mt * 16 + (sel & 1) * 8 + q) * 80
                 + (uint32_t)(sel >> 1) * 16;
#pragma unroll
    for (int nb = 0; nb < 2; nb++)
        boff[nb] = (uint32_t)(wc * 32 + nb * 16 + (sel >> 1) * 8 + q) * 80
                 + (uint32_t)(sel & 1) * 16;

    const int n = K >> 5;   // K / 32 chunks

    ld_stage(smb,           Ah, Al, Bh, Bl, K, 0,  tid); CP_COMMIT();
    ld_stage(smb + STAGE_B, Ah, Al, Bh, Bl, K, 32, tid); CP_COMMIT();

    float acc[4][4][4];
#pragma unroll
    for (int mt = 0; mt < 4; mt++)
#pragma unroll
        for (int nt = 0; nt < 4; nt++)
#pragma unroll
            for (int r = 0; r < 4; r++) acc[mt][nt][r] = 0.0f;

    for (int i = 0; i < n; i++) {
        if (i + 2 < n)
            ld_stage(smb + ((i + 2) & 3) * STAGE_B, Ah, Al, Bh, Bl, K,
                     (i + 2) * 32, tid);
        CP_COMMIT();
        CP_WAIT2();
        __syncthreads();

        const uint32_t sb = smb + (i & 3) * STAGE_B;
#pragma unroll
        for (int ks = 0; ks < 2; ks++) {
            uint32_t ah[4][4], al[4][4], bh[2][4], bl[2][4];
#pragma unroll
            for (int mt = 0; mt < 4; mt++) {
                uint32_t ad = sb + aoff[mt] + ks * 32;
                LDM4(ah[mt], ad);
                LDM4(al[mt], ad + PLANE_B);
            }
#pragma unroll
            for (int nb = 0; nb < 2; nb++) {
                uint32_t bd = sb + 2 * PLANE_B + boff[nb] + ks * 32;
                LDM4(bh[nb], bd);
                LDM4(bl[nb], bd + PLANE_B);
            }
#pragma unroll
            for (int mt = 0; mt < 4; mt++)
#pragma unroll
                for (int nt = 0; nt < 4; nt++) {
                    const uint32_t* B0 = &bh[nt >> 1][(nt & 1) * 2];
                    const uint32_t* B1 = &bl[nt >> 1][(nt & 1) * 2];
                    MMA16816(acc[mt][nt], ah[mt], B0[0], B0[1]);
                    MMA16816(acc[mt][nt], ah[mt], B1[0], B1[1]);
                    MMA16816(acc[mt][nt], al[mt], B0[0], B0[1]);
                }
        }
    }

    // epilogue
#pragma unroll
    for (int mt = 0; mt < 4; mt++)
#pragma unroll
        for (int nt = 0; nt < 4; nt++) {
            int r0 = wr * 64 + mt * 16 + g;
            int c0 = wc * 32 + nt * 8 + 2 * t;
            if (EPI == 0) {
                float2 v0, v1;
                v0.x = alpha * acc[mt][nt][0]; v0.y = alpha * acc[mt][nt][1];
                v1.x = alpha * acc[mt][nt][2]; v1.y = alpha * acc[mt][nt][3];
                *(float2*)(C + (size_t)r0 * ldC + c0)       = v0;
                *(float2*)(C + (size_t)(r0 + 8) * ldC + c0) = v1;
            } else {
#pragma unroll
                for (int hh = 0; hh < 2; hh++) {
                    float v0 = acc[mt][nt][2 * hh + 0];
                    float v1 = acc[mt][nt][2 * hh + 1];
                    __nv_bfloat16 h0 = __float2bfloat16(v0);
                    __nv_bfloat16 h1 = __float2bfloat16(v1);
                    __nv_bfloat16 l0 = __float2bfloat16(v0 - __bfloat162float(h0));
                    __nv_bfloat16 l1 = __float2bfloat16(v1 - __bfloat162float(h1));
                    __nv_bfloat162 hp; hp.x = h0; hp.y = h1;
                    __nv_bfloat162 lp; lp.x = l0; lp.y = l1;
                    size_t off = (size_t)(r0 + 8 * hh) * ldC + c0;
                    *(__nv_bfloat162*)(Ch + off) = hp;
                    *(__nv_bfloat162*)(Cl + off) = lp;
                }
            }
        }
}

// ---------------- GEMM wrapper kernels -------------------------------------
__global__ void __launch_bounds__(256) k_gemm_proj() {
    const int z = blockIdx.z;
    const size_t a0 = (size_t)blockIdx.y * 128 * FDIM;
    const size_t b0 = (size_t)z * FDIM * DDIM + (size_t)blockIdx.x * 128 * FDIM;
    __nv_bfloat16* Ch = (z == 0) ? g_Q_h : (z == 1) ? g_K_h : g_V_h;
    __nv_bfloat16* Cl = (z == 0) ? g_Q_l : (z == 1) ? g_K_l : g_V_l;
    const size_t c0 = (size_t)blockIdx.y * 128 * DDIM + blockIdx.x * 128;
    gemm_core<1>(g_xpe_h + a0, g_xpe_l + a0, g_Wt_h + b0, g_Wt_l + b0,
                 FDIM, 1.0f, nullptr, DDIM, Ch + c0, Cl + c0);
}

__global__ void __launch_bounds__(256) k_gemm_scores() {
    const size_t b = blockIdx.z;
    const size_t a0 = b * SEQ * DDIM + (size_t)blockIdx.y * 128 * DDIM;
    const size_t b0 = b * SEQ * DDIM + (size_t)blockIdx.x * 128 * DDIM;
    const size_t c0 = b * SEQ * SEQ + (size_t)blockIdx.y * 128 * SEQ + blockIdx.x * 128;
    gemm_core<0>(g_Q_h + a0, g_Q_l + a0, g_K_h + b0, g_K_l + b0,
                 DDIM, 0.04419417382415922f, g_scores + c0, SEQ, nullptr, nullptr);
}

__global__ void __launch_bounds__(256) k_gemm_av(float* __restrict__ out) {
    const size_t b = blockIdx.z;
    const size_t a0 = b * SEQ * SEQ + (size_t)blockIdx.y * 128 * SEQ;
    const size_t b0 = b * DDIM * SEQ + (size_t)blockIdx.x * 128 * SEQ;
    const size_t c0 = b * SEQ * DDIM + (size_t)blockIdx.y * 128 * DDIM + blockIdx.x * 128;
    gemm_core<0>(g_attn_h + a0, g_attn_l + a0, g_Vt_h + b0, g_Vt_l + b0,
                 SEQ, 1.0f, out + c0, DDIM, nullptr, nullptr);
}

// ---------------- aux kernels ----------------------------------------------
__global__ void __launch_bounds__(256) k_addpe_split(const float* __restrict__ x) {
    size_t idx = (size_t)blockIdx.x * 256 + threadIdx.x;
    int f = (int)(idx & (FDIM - 1));
    int s = (int)((idx >> 9) & (SEQ - 1));
    float e     = (float)(f & ~1) * (1.0f / (float)FDIM);
    float denom = powf(10000.0f, e);
    float angle = (float)s / denom;
    double r = fmod((double)angle, 6.283185307179586476925286766559);
    float a = (float)r;
    float pe = (f & 1) ? cosf(a) : sinf(a);
    float v = x[idx] + pe;
    __nv_bfloat16 h = __float2bfloat16(v);
    g_xpe_h[idx] = h;
    g_xpe_l[idx] = __float2bfloat16(v - __bfloat162float(h));
}

// transpose + split W: Wt[z][n][k] = W[z][k][n]
__global__ void __launch_bounds__(256) k_splitW(const float* __restrict__ Wq,
                                                const float* __restrict__ Wk,
                                                const float* __restrict__ Wv) {
    __shared__ float tsm[32][33];
    const int z = blockIdx.z;
    const float* W = (z == 0) ? Wq : (z == 1) ? Wk : Wv;
    const int k0 = blockIdx.y * 32, n0 = blockIdx.x * 32;
    const int tx = threadIdx.x & 31, ty = threadIdx.x >> 5;  // 32 x 8
#pragma unroll
    for (int i = 0; i < 32; i += 8)
        tsm[ty + i][tx] = W[(size_t)(k0 + ty + i) * DDIM + n0 + tx];
    __syncthreads();
#pragma unroll
    for (int i = 0; i < 32; i += 8) {
        float v = tsm[tx][ty + i];
        __nv_bfloat16 h = __float2bfloat16(v);
        size_t off = (size_t)z * FDIM * DDIM + (size_t)(n0 + ty + i) * FDIM + k0 + tx;
        g_Wt_h[off] = h;
        g_Wt_l[off] = __float2bfloat16(v - __bfloat162float(h));
    }
}

// transpose V planes: Vt[b][d][j] = V[b*2048+j][d]
__global__ void __launch_bounds__(256) k_transV() {
    __shared__ __nv_bfloat16 th[32][33];
    __shared__ __nv_bfloat16 tl[32][33];
    const int b = blockIdx.z;
    const int d0 = blockIdx.x * 32, j0 = blockIdx.y * 32;
    const int tx = threadIdx.x & 31, ty = threadIdx.x >> 5;
#pragma unroll
    for (int i = 0; i < 32; i += 8) {
        size_t off = (size_t)(b * SEQ + j0 + ty + i) * DDIM + d0 + tx;
        th[ty + i][tx] = g_V_h[off];
        tl[ty + i][tx] = g_V_l[off];
    }
    __syncthreads();
#pragma unroll
    for (int i = 0; i < 32; i += 8) {
        size_t off = (size_t)b * DDIM * SEQ + (size_t)(d0 + ty + i) * SEQ + j0 + tx;
        g_Vt_h[off] = th[tx][ty + i];
        g_Vt_l[off] = tl[tx][ty + i];
    }
}

// softmax over 2048 cols + split to bf16 planes
__global__ void __launch_bounds__(256) k_softmax_split() {
    const size_t rowoff = (size_t)blockIdx.x * SEQ;
    const float* p = g_scores + rowoff;
    const int tid = threadIdx.x;
    float v[8];
    float m = -1e30f;
#pragma unroll
    for (int i = 0; i < 8; i++) {
        v[i] = p[tid + i * 256];
        m = fmaxf(m, v[i]);
    }
    __shared__ float sh[8];
#pragma unroll
    for (int o = 16; o > 0; o >>= 1)
        m = fmaxf(m, __shfl_xor_sync(0xffffffffu, m, o));
    if ((tid & 31) == 0) sh[tid >> 5] = m;
    __syncthreads();
    m = sh[0];
#pragma unroll
    for (int w = 1; w < 8; w++) m = fmaxf(m, sh[w]);

    float s = 0.0f;
#pragma unroll
    for (int i = 0; i < 8; i++) {
        v[i] = expf(v[i] - m);
        s += v[i];
    }
#pragma unroll
    for (int o = 16; o > 0; o >>= 1)
        s += __shfl_xor_sync(0xffffffffu, s, o);
    __syncthreads();
    if ((tid & 31) == 0) sh[tid >> 5] = s;
    __syncthreads();
    s = 0.0f;
#pragma unroll
    for (int w = 0; w < 8; w++) s += sh[w];
    const float inv = 1.0f / s;
#pragma unroll
    for (int i = 0; i < 8; i++) {
        float a = v[i] * inv;
        __nv_bfloat16 h = __float2bfloat16(a);
        g_attn_h[rowoff + tid + i * 256] = h;
        g_attn_l[rowoff + tid + i * 256] = __float2bfloat16(a - __bfloat162float(h));
    }
}

// ---------------- launch ----------------------------------------------------
extern "C" void kernel_launch(void* const* d_in, const int* in_sizes, int n_in,
                              void* d_out, int out_size)
{
    const float* x  = (const float*)d_in[0];
    const float* Wq = (const float*)d_in[1];
    const float* Wk = (const float*)d_in[2];
    const float* Wv = (const float*)d_in[3];
    float* out = (float*)d_out;

    cudaFuncSetAttribute(k_gemm_proj,   cudaFuncAttributeMaxDynamicSharedMemorySize, SMEM_TOTAL);
    cudaFuncSetAttribute(k_gemm_scores, cudaFuncAttributeMaxDynamicSharedMemorySize, SMEM_TOTAL);
    cudaFuncSetAttribute(k_gemm_av,     cudaFuncAttributeMaxDynamicSharedMemorySize, SMEM_TOTAL);

    k_addpe_split<<<((size_t)MTOT * FDIM) / 256, 256>>>(x);
    k_splitW<<<dim3(DDIM / 32, FDIM / 32, 3), 256>>>(Wq, Wk, Wv);
    k_gemm_proj<<<dim3(DDIM / 128, MTOT / 128, 3), 256, SMEM_TOTAL>>>();
    k_transV<<<dim3(DDIM / 32, SEQ / 32, BATCH), 256>>>();
    k_gemm_scores<<<dim3(SEQ / 128, SEQ / 128, BATCH), 256, SMEM_TOTAL>>>();
    k_softmax_split<<<BATCH * SEQ, 256>>>();
    k_gemm_av<<<dim3(DDIM / 128, SEQ / 128, BATCH), 256, SMEM_TOTAL>>>(out);
}

// round 5
// speedup vs baseline: 2.5589x; 1.0095x over previous
#include <cuda_runtime.h>
#include <cuda_bf16.h>
#include <math.h>
#include <stdint.h>

#define BATCH 8
#define SEQ   2048
#define FDIM  512
#define DDIM  512
#define MTOT  (BATCH * SEQ)   // 16384

// ---------------- scratch (__device__ globals; no allocs allowed) ----------
__device__ __nv_bfloat16 g_xpe_h[(size_t)MTOT * FDIM];
__device__ __nv_bfloat16 g_xpe_l[(size_t)MTOT * FDIM];
__device__ __nv_bfloat16 g_Wt_h[3 * FDIM * DDIM];      // [z][n][k] (W transposed)
__device__ __nv_bfloat16 g_Wt_l[3 * FDIM * DDIM];
__device__ __nv_bfloat16 g_Q_h[(size_t)MTOT * DDIM];
__device__ __nv_bfloat16 g_Q_l[(size_t)MTOT * DDIM];
__device__ __nv_bfloat16 g_K_h[(size_t)MTOT * DDIM];
__device__ __nv_bfloat16 g_K_l[(size_t)MTOT * DDIM];
__device__ __nv_bfloat16 g_V_h[(size_t)MTOT * DDIM];
__device__ __nv_bfloat16 g_V_l[(size_t)MTOT * DDIM];
__device__ __nv_bfloat16 g_Vt_h[(size_t)MTOT * DDIM];  // [b][d][j]
__device__ __nv_bfloat16 g_Vt_l[(size_t)MTOT * DDIM];
__device__ float         g_scores[(size_t)BATCH * SEQ * SEQ];     // 134MB
__device__ __nv_bfloat16 g_attn_h[(size_t)BATCH * SEQ * SEQ];
__device__ __nv_bfloat16 g_attn_l[(size_t)BATCH * SEQ * SEQ];

// ---------------- PTX helpers ----------------------------------------------
__device__ __forceinline__ uint32_t s2u(const void* p) {
    return (uint32_t)__cvta_generic_to_shared(p);
}
__device__ __forceinline__ void cpa16(uint32_t dst, const void* src) {
    asm volatile("cp.async.cg.shared.global [%0], [%1], 16;\n" :: "r"(dst), "l"(src));
}
#define CP_COMMIT()  asm volatile("cp.async.commit_group;\n" ::: "memory")
#define CP_WAIT2()   asm volatile("cp.async.wait_group 2;\n" ::: "memory")

#define LDM4(r, addr) \
    asm volatile("ldmatrix.sync.aligned.m8n8.x4.shared.b16 {%0,%1,%2,%3}, [%4];" \
                 : "=r"((r)[0]), "=r"((r)[1]), "=r"((r)[2]), "=r"((r)[3]) : "r"(addr))

#define MMA16816(d, a, b0, b1) \
    asm volatile("mma.sync.aligned.m16n8k16.row.col.f32.bf16.bf16.f32 " \
                 "{%0,%1,%2,%3}, {%4,%5,%6,%7}, {%8,%9}, {%0,%1,%2,%3};" \
                 : "+f"((d)[0]), "+f"((d)[1]), "+f"((d)[2]), "+f"((d)[3]) \
                 : "r"((a)[0]), "r"((a)[1]), "r"((a)[2]), "r"((a)[3]), \
                   "r"(b0), "r"(b1))

// ---------------- GEMM: CTA 128x128, K-chunk 32, bf16x3, HMMA --------------
// smem per stage: 4 planes (Ah, Al, Bh, Bl), each 128 rows x 80B (32 bf16 + pad)
#define PLANE_B    10240
#define STAGE_B    40960
#define SMEM_TOTAL (4 * STAGE_B)   // 163840

__device__ __forceinline__ void ld_stage(uint32_t sb,
    const __nv_bfloat16* Ah, const __nv_bfloat16* Al,
    const __nv_bfloat16* Bh, const __nv_bfloat16* Bl,
    int K, int k0, int tid)
{
#pragma unroll
    for (int i = 0; i < 2; i++) {
        int ci = tid + i * 256;
        int r = ci >> 2, c = ci & 3;
        size_t ge = (size_t)r * K + k0 + c * 8;   // bf16 element offset
        uint32_t so = r * 80 + c * 16;
        cpa16(sb + so,               Ah + ge);
        cpa16(sb + PLANE_B + so,     Al + ge);
        cpa16(sb + 2 * PLANE_B + so, Bh + ge);
        cpa16(sb + 3 * PLANE_B + so, Bl + ge);
    }
}

// EPI 0: fp32 C with alpha.  EPI 1: bf16 hi/lo split planes.
template <int EPI>
__device__ __forceinline__ void gemm_core(
    const __nv_bfloat16* __restrict__ Ah, const __nv_bfloat16* __restrict__ Al,
    const __nv_bfloat16* __restrict__ Bh, const __nv_bfloat16* __restrict__ Bl,
    int K, float alpha,
    float* __restrict__ C, int ldC,
    __nv_bfloat16* __restrict__ Ch, __nv_bfloat16* __restrict__ Cl)
{
    extern __shared__ __align__(128) char sm[];
    const uint32_t smb = s2u(sm);
    const int tid = threadIdx.x;
    const int w = tid >> 5, lane = tid & 31;
    const int wr = w & 1, wc = w >> 1;         // warp grid 2 (M) x 4 (N)
    const int q = lane & 7, sel = lane >> 3;   // ldmatrix addressing
    const int g = lane >> 2, t = lane & 3;     // fragment addressing

    // per-thread ldmatrix smem byte offsets (within plane); ks adds ks*32
    uint32_t aoff[4], boff[2];
#pragma unroll
    for (int mt = 0; mt < 4; mt++)
        aoff[mt] = (uint32_t)(wr * 64 + mt * 16 + (sel & 1) * 8 + q) * 80
                 + (uint32_t)(sel >> 1) * 16;
#pragma unroll
    for (int nb = 0; nb < 2; nb++)
        boff[nb] = (uint32_t)(wc * 32 + nb * 16 + (sel >> 1) * 8 + q) * 80
                 + (uint32_t)(sel & 1) * 16;

    const int n = K >> 5;   // K / 32 chunks

    ld_stage(smb,           Ah, Al, Bh, Bl, K, 0,  tid); CP_COMMIT();
    ld_stage(smb + STAGE_B, Ah, Al, Bh, Bl, K, 32, tid); CP_COMMIT();

    float acc[4][4][4];
#pragma unroll
    for (int mt = 0; mt < 4; mt++)
#pragma unroll
        for (int nt = 0; nt < 4; nt++)
#pragma unroll
            for (int r = 0; r < 4; r++) acc[mt][nt][r] = 0.0f;

    for (int i = 0; i < n; i++) {
        if (i + 2 < n)
            ld_stage(smb + ((i + 2) & 3) * STAGE_B, Ah, Al, Bh, Bl, K,
                     (i + 2) * 32, tid);
        CP_COMMIT();
        CP_WAIT2();
        __syncthreads();

        const uint32_t sb = smb + (i & 3) * STAGE_B;
#pragma unroll
        for (int ks = 0; ks < 2; ks++) {
            uint32_t ah[4][4], al[4][4], bh[2][4], bl[2][4];
#pragma unroll
            for (int mt = 0; mt < 4; mt++) {
                uint32_t ad = sb + aoff[mt] + ks * 32;
                LDM4(ah[mt], ad);
                LDM4(al[mt], ad + PLANE_B);
            }
#pragma unroll
            for (int nb = 0; nb < 2; nb++) {
                uint32_t bd = sb + 2 * PLANE_B + boff[nb] + ks * 32;
                LDM4(bh[nb], bd);
                LDM4(bl[nb], bd + PLANE_B);
            }
            // term-major issue order: all hi*hi, then hi*lo, then lo*hi.
            // Dependent MMAs on the same accumulator are 16 instructions apart,
            // which hides the HMMA latency inside the issue stream.
#pragma unroll
            for (int mt = 0; mt < 4; mt++)
#pragma unroll
                for (int nt = 0; nt < 4; nt++) {
                    const uint32_t* B0 = &bh[nt >> 1][(nt & 1) * 2];
                    MMA16816(acc[mt][nt], ah[mt], B0[0], B0[1]);
                }
#pragma unroll
            for (int mt = 0; mt < 4; mt++)
#pragma unroll
                for (int nt = 0; nt < 4; nt++) {
                    const uint32_t* B1 = &bl[nt >> 1][(nt & 1) * 2];
                    MMA16816(acc[mt][nt], ah[mt], B1[0], B1[1]);
                }
#pragma unroll
            for (int mt = 0; mt < 4; mt++)
#pragma unroll
                for (int nt = 0; nt < 4; nt++) {
                    const uint32_t* B0 = &bh[nt >> 1][(nt & 1) * 2];
                    MMA16816(acc[mt][nt], al[mt], B0[0], B0[1]);
                }
        }
    }

    // epilogue
#pragma unroll
    for (int mt = 0; mt < 4; mt++)
#pragma unroll
        for (int nt = 0; nt < 4; nt++) {
            int r0 = wr * 64 + mt * 16 + g;
            int c0 = wc * 32 + nt * 8 + 2 * t;
            if (EPI == 0) {
                float2 v0, v1;
                v0.x = alpha * acc[mt][nt][0]; v0.y = alpha * acc[mt][nt][1];
                v1.x = alpha * acc[mt][nt][2]; v1.y = alpha * acc[mt][nt][3];
                *(float2*)(C + (size_t)r0 * ldC + c0)       = v0;
                *(float2*)(C + (size_t)(r0 + 8) * ldC + c0) = v1;
            } else {
#pragma unroll
                for (int hh = 0; hh < 2; hh++) {
                    float v0 = acc[mt][nt][2 * hh + 0];
                    float v1 = acc[mt][nt][2 * hh + 1];
                    __nv_bfloat16 h0 = __float2bfloat16(v0);
                    __nv_bfloat16 h1 = __float2bfloat16(v1);
                    __nv_bfloat16 l0 = __float2bfloat16(v0 - __bfloat162float(h0));
                    __nv_bfloat16 l1 = __float2bfloat16(v1 - __bfloat162float(h1));
                    __nv_bfloat162 hp; hp.x = h0; hp.y = h1;
                    __nv_bfloat162 lp; lp.x = l0; lp.y = l1;
                    size_t off = (size_t)(r0 + 8 * hh) * ldC + c0;
                    *(__nv_bfloat162*)(Ch + off) = hp;
                    *(__nv_bfloat162*)(Cl + off) = lp;
                }
            }
        }
}

// ---------------- GEMM wrapper kernels -------------------------------------
__global__ void __launch_bounds__(256) k_gemm_proj() {
    const int z = blockIdx.z;
    const size_t a0 = (size_t)blockIdx.y * 128 * FDIM;
    const size_t b0 = (size_t)z * FDIM * DDIM + (size_t)blockIdx.x * 128 * FDIM;
    __nv_bfloat16* Ch = (z == 0) ? g_Q_h : (z == 1) ? g_K_h : g_V_h;
    __nv_bfloat16* Cl = (z == 0) ? g_Q_l : (z == 1) ? g_K_l : g_V_l;
    const size_t c0 = (size_t)blockIdx.y * 128 * DDIM + blockIdx.x * 128;
    gemm_core<1>(g_xpe_h + a0, g_xpe_l + a0, g_Wt_h + b0, g_Wt_l + b0,
                 FDIM, 1.0f, nullptr, DDIM, Ch + c0, Cl + c0);
}

__global__ void __launch_bounds__(256) k_gemm_scores() {
    const size_t b = blockIdx.z;
    const size_t a0 = b * SEQ * DDIM + (size_t)blockIdx.y * 128 * DDIM;
    const size_t b0 = b * SEQ * DDIM + (size_t)blockIdx.x * 128 * DDIM;
    const size_t c0 = b * SEQ * SEQ + (size_t)blockIdx.y * 128 * SEQ + blockIdx.x * 128;
    gemm_core<0>(g_Q_h + a0, g_Q_l + a0, g_K_h + b0, g_K_l + b0,
                 DDIM, 0.04419417382415922f, g_scores + c0, SEQ, nullptr, nullptr);
}

__global__ void __launch_bounds__(256) k_gemm_av(float* __restrict__ out) {
    const size_t b = blockIdx.z;
    const size_t a0 = b * SEQ * SEQ + (size_t)blockIdx.y * 128 * SEQ;
    const size_t b0 = b * DDIM * SEQ + (size_t)blockIdx.x * 128 * SEQ;
    const size_t c0 = b * SEQ * DDIM + (size_t)blockIdx.y * 128 * DDIM + blockIdx.x * 128;
    gemm_core<0>(g_attn_h + a0, g_attn_l + a0, g_Vt_h + b0, g_Vt_l + b0,
                 SEQ, 1.0f, out + c0, DDIM, nullptr, nullptr);
}

// ---------------- aux kernels ----------------------------------------------
__global__ void __launch_bounds__(256) k_addpe_split(const float* __restrict__ x) {
    size_t idx = (size_t)blockIdx.x * 256 + threadIdx.x;
    int f = (int)(idx & (FDIM - 1));
    int s = (int)((idx >> 9) & (SEQ - 1));
    float e     = (float)(f & ~1) * (1.0f / (float)FDIM);
    float denom = powf(10000.0f, e);
    float angle = (float)s / denom;
    double r = fmod((double)angle, 6.283185307179586476925286766559);
    float a = (float)r;
    float pe = (f & 1) ? cosf(a) : sinf(a);
    float v = x[idx] + pe;
    __nv_bfloat16 h = __float2bfloat16(v);
    g_xpe_h[idx] = h;
    g_xpe_l[idx] = __float2bfloat16(v - __bfloat162float(h));
}

// transpose + split W: Wt[z][n][k] = W[z][k][n]
__global__ void __launch_bounds__(256) k_splitW(const float* __restrict__ Wq,
                                                const float* __restrict__ Wk,
                                                const float* __restrict__ Wv) {
    __shared__ float tsm[32][33];
    const int z = blockIdx.z;
    const float* W = (z == 0) ? Wq : (z == 1) ? Wk : Wv;
    const int k0 = blockIdx.y * 32, n0 = blockIdx.x * 32;
    const int tx = threadIdx.x & 31, ty = threadIdx.x >> 5;  // 32 x 8
#pragma unroll
    for (int i = 0; i < 32; i += 8)
        tsm[ty + i][tx] = W[(size_t)(k0 + ty + i) * DDIM + n0 + tx];
    __syncthreads();
#pragma unroll
    for (int i = 0; i < 32; i += 8) {
        float v = tsm[tx][ty + i];
        __nv_bfloat16 h = __float2bfloat16(v);
        size_t off = (size_t)z * FDIM * DDIM + (size_t)(n0 + ty + i) * FDIM + k0 + tx;
        g_Wt_h[off] = h;
        g_Wt_l[off] = __float2bfloat16(v - __bfloat162float(h));
    }
}

// transpose V planes: Vt[b][d][j] = V[b*2048+j][d]
__global__ void __launch_bounds__(256) k_transV() {
    __shared__ __nv_bfloat16 th[32][33];
    __shared__ __nv_bfloat16 tl[32][33];
    const int b = blockIdx.z;
    const int d0 = blockIdx.x * 32, j0 = blockIdx.y * 32;
    const int tx = threadIdx.x & 31, ty = threadIdx.x >> 5;
#pragma unroll
    for (int i = 0; i < 32; i += 8) {
        size_t off = (size_t)(b * SEQ + j0 + ty + i) * DDIM + d0 + tx;
        th[ty + i][tx] = g_V_h[off];
        tl[ty + i][tx] = g_V_l[off];
    }
    __syncthreads();
#pragma unroll
    for (int i = 0; i < 32; i += 8) {
        size_t off = (size_t)b * DDIM * SEQ + (size_t)(d0 + ty + i) * SEQ + j0 + tx;
        g_Vt_h[off] = th[tx][ty + i];
        g_Vt_l[off] = tl[tx][ty + i];
    }
}

// softmax over 2048 cols + split to bf16 planes
__global__ void __launch_bounds__(256) k_softmax_split() {
    const size_t rowoff = (size_t)blockIdx.x * SEQ;
    const float* p = g_scores + rowoff;
    const int tid = threadIdx.x;
    float v[8];
    float m = -1e30f;
#pragma unroll
    for (int i = 0; i < 8; i++) {
        v[i] = p[tid + i * 256];
        m = fmaxf(m, v[i]);
    }
    __shared__ float sh[8];
#pragma unroll
    for (int o = 16; o > 0; o >>= 1)
        m = fmaxf(m, __shfl_xor_sync(0xffffffffu, m, o));
    if ((tid & 31) == 0) sh[tid >> 5] = m;
    __syncthreads();
    m = sh[0];
#pragma unroll
    for (int w = 1; w < 8; w++) m = fmaxf(m, sh[w]);

    float s = 0.0f;
#pragma unroll
    for (int i = 0; i < 8; i++) {
        v[i] = expf(v[i] - m);
        s += v[i];
    }
#pragma unroll
    for (int o = 16; o > 0; o >>= 1)
        s += __shfl_xor_sync(0xffffffffu, s, o);
    __syncthreads();
    if ((tid & 31) == 0) sh[tid >> 5] = s;
    __syncthreads();
    s = 0.0f;
#pragma unroll
    for (int w = 0; w < 8; w++) s += sh[w];
    const float inv = 1.0f / s;
#pragma unroll
    for (int i = 0; i < 8; i++) {
        float a = v[i] * inv;
        __nv_bfloat16 h = __float2bfloat16(a);
        g_attn_h[rowoff + tid + i * 256] = h;
        g_attn_l[rowoff + tid + i * 256] = __float2bfloat16(a - __bfloat162float(h));
    }
}

// ---------------- launch ----------------------------------------------------
extern "C" void kernel_launch(void* const* d_in, const int* in_sizes, int n_in,
                              void* d_out, int out_size)
{
    const float* x  = (const float*)d_in[0];
    const float* Wq = (const float*)d_in[1];
    const float* Wk = (const float*)d_in[2];
    const float* Wv = (const float*)d_in[3];
    float* out = (float*)d_out;

    cudaFuncSetAttribute(k_gemm_proj,   cudaFuncAttributeMaxDynamicSharedMemorySize, SMEM_TOTAL);
    cudaFuncSetAttribute(k_gemm_scores, cudaFuncAttributeMaxDynamicSharedMemorySize, SMEM_TOTAL);
    cudaFuncSetAttribute(k_gemm_av,     cudaFuncAttributeMaxDynamicSharedMemorySize, SMEM_TOTAL);

    k_addpe_split<<<((size_t)MTOT * FDIM) / 256, 256>>>(x);
    k_splitW<<<dim3(DDIM / 32, FDIM / 32, 3), 256>>>(Wq, Wk, Wv);
    k_gemm_proj<<<dim3(DDIM / 128, MTOT / 128, 3), 256, SMEM_TOTAL>>>();
    k_transV<<<dim3(DDIM / 32, SEQ / 32, BATCH), 256>>>();
    k_gemm_scores<<<dim3(SEQ / 128, SEQ / 128, BATCH), 256, SMEM_TOTAL>>>();
    k_softmax_split<<<BATCH * SEQ, 256>>>();
    k_gemm_av<<<dim3(DDIM / 128, SEQ / 128, BATCH), 256, SMEM_TOTAL>>>(out);
}